// round 1
// baseline (speedup 1.0000x reference)
#include <cuda_runtime.h>
#include <math.h>

#define T_TOK 2048
#define NE 64
#define KTOP 8
#define SELK 4
#define HD 2048
#define FI 768
#define TWOF 1536
#define BM 64
#define BN 64
#define BK 16
#define MAXMT 320            // sum ceil(cnt/BM) <= 16384/64 + 64
#define CAP 20480            // 16384 + 64*64 padded rows

// ---------------- scratch (device globals; no runtime allocation) ----------------
__device__ float d_topv[T_TOK * KTOP];
__device__ int   d_topi[T_TOK * KTOP];
__device__ int   d_rer[T_TOK * KTOP];
__device__ unsigned int d_pmask[2];
__device__ unsigned int d_smask[2];
__device__ int d_map[NE];
__device__ int d_counts[NE];
__device__ int d_padoff[NE];
__device__ int d_cursor[NE];
__device__ int d_tile_e[MAXMT];
__device__ int d_tile_base[MAXMT];
__device__ int d_tile_lim[MAXMT];
__device__ int d_nmt;
__device__ int d_totalpad;
__device__ int d_row_src[CAP];
__device__ float d_row_w[CAP];
__device__ int d_row_of[T_TOK * KTOP];
__device__ float d_gu[(size_t)CAP * TWOF];     // gate|up pre-activation
__device__ float d_hact[(size_t)CAP * FI];     // silu(gate)*up
__device__ float d_y[(size_t)CAP * HD];        // weighted expert outputs

// ---------------- reset mutable state (graph replays must be idempotent) ----------
__global__ void zero_kernel() {
    int i = threadIdx.x;
    if (i < NE) d_counts[i] = 0;
    if (i < 2) { d_pmask[i] = 0u; d_smask[i] = 0u; }
}

// ---------------- router: logits -> softmax -> top8 -> renorm + global masks ------
__global__ void router_kernel(const float* __restrict__ x, const float* __restrict__ gw) {
    __shared__ float sx[HD];
    __shared__ float sl[NE];
    int t = blockIdx.x;
    const float* xr = x + (size_t)t * HD;
    for (int i = threadIdx.x; i < HD; i += blockDim.x) sx[i] = xr[i];
    __syncthreads();

    int e   = threadIdx.x >> 2;   // 0..63
    int sub = threadIdx.x & 3;    // 0..3 quarter of H
    const float4* wp = (const float4*)(gw + (size_t)e * HD + sub * (HD / 4));
    const float4* xp = (const float4*)(sx + sub * (HD / 4));
    float s = 0.f;
#pragma unroll 4
    for (int i = 0; i < HD / 16; i++) {
        float4 a = xp[i]; float4 w = wp[i];
        s += a.x * w.x + a.y * w.y + a.z * w.z + a.w * w.w;
    }
    s += __shfl_xor_sync(0xffffffffu, s, 1);
    s += __shfl_xor_sync(0xffffffffu, s, 2);
    if (sub == 0) sl[e] = s;
    __syncthreads();

    if (threadIdx.x < 32) {
        int lane = threadIdx.x;
        float v0 = sl[lane], v1 = sl[lane + 32];
        float m = fmaxf(v0, v1);
        for (int off = 16; off; off >>= 1) m = fmaxf(m, __shfl_xor_sync(0xffffffffu, m, off));
        float e0 = expf(v0 - m), e1 = expf(v1 - m);
        float ss = e0 + e1;
        for (int off = 16; off; off >>= 1) ss += __shfl_xor_sync(0xffffffffu, ss, off);
        float p0 = e0 / ss, p1 = e1 / ss;

        float tv[KTOP]; int ti[KTOP];
#pragma unroll
        for (int k = 0; k < KTOP; k++) {
            float b; int bi;
            if (p0 >= p1) { b = p0; bi = lane; } else { b = p1; bi = lane + 32; }
            for (int off = 16; off; off >>= 1) {
                float ob = __shfl_xor_sync(0xffffffffu, b, off);
                int obi  = __shfl_xor_sync(0xffffffffu, bi, off);
                if (ob > b || (ob == b && obi < bi)) { b = ob; bi = obi; }
            }
            tv[k] = b; ti[k] = bi;
            if (bi < 32) { if (lane == bi) p0 = -1.f; }
            else         { if (lane == bi - 32) p1 = -1.f; }
        }
        if (lane == 0) {
            float tsum = 0.f;
#pragma unroll
            for (int k = 0; k < KTOP; k++) tsum += tv[k];
            tsum = fmaxf(tsum, 1e-12f);
#pragma unroll
            for (int k = 0; k < KTOP; k++) {
                d_topv[t * KTOP + k] = tv[k] / tsum;
                d_topi[t * KTOP + k] = ti[k];
                int b = ti[k];
                if (k < SELK) atomicOr(&d_pmask[b >> 5], 1u << (b & 31));
                else          atomicOr(&d_smask[b >> 5], 1u << (b & 31));
            }
        }
    }
}

// ---------------- SERE mapping over global masks ----------------
__global__ void mapping_kernel(const float* __restrict__ sim) {
    int e = threadIdx.x;
    if (e >= NE) return;
    unsigned pm0 = d_pmask[0], pm1 = d_pmask[1];
    unsigned sm0 = d_smask[0], sm1 = d_smask[1];
    bool prim = (e < 32) ? ((pm0 >> e) & 1) : ((pm1 >> (e - 32)) & 1);
    bool sec  = (e < 32) ? ((sm0 >> e) & 1) : ((sm1 >> (e - 32)) & 1);
    int best = 0; float bs = -INFINITY;
    for (int p = 0; p < NE; p++) {
        bool pp = (p < 32) ? ((pm0 >> p) & 1) : ((pm1 >> (p - 32)) & 1);
        if (!pp) continue;
        float v = (p == e) ? 1.0f : sim[e * NE + p];
        if (v > bs) { bs = v; best = p; }   // strict > => first max (argmax semantics)
    }
    int mp = e;
    if (sec && !prim && bs >= 0.5f) mp = best;
    d_map[e] = mp;
}

// ---------------- reroute + per-expert counts ----------------
__global__ void reroute_kernel() {
    int a = blockIdx.x * blockDim.x + threadIdx.x;
    if (a >= T_TOK * KTOP) return;
    int k = a & 7;
    int e0 = d_topi[a];
    int e = (k < SELK) ? e0 : d_map[e0];
    d_rer[a] = e;
    atomicAdd(&d_counts[e], 1);
}

// ---------------- padded offsets + GEMM tile table (serial, tiny) ----------------
__global__ void build_tiles_kernel() {
    if (threadIdx.x != 0 || blockIdx.x != 0) return;
    int off = 0, nt = 0;
    for (int e = 0; e < NE; e++) {
        d_padoff[e] = off;
        d_cursor[e] = 0;
        int c = d_counts[e];
        int mt = (c + BM - 1) / BM;
        for (int i = 0; i < mt; i++) {
            d_tile_e[nt] = e;
            d_tile_base[nt] = off + i * BM;
            int lm = c - i * BM; if (lm > BM) lm = BM;
            d_tile_lim[nt] = lm;
            nt++;
        }
        off += mt * BM;
    }
    d_nmt = nt;
    d_totalpad = off;
}

// ---------------- scatter assignments into expert-sorted rows ----------------
__global__ void scatter_kernel() {
    int a = blockIdx.x * blockDim.x + threadIdx.x;
    if (a >= T_TOK * KTOP) return;
    int e = d_rer[a];
    int pos = d_padoff[e] + atomicAdd(&d_cursor[e], 1);
    d_row_src[pos] = a >> 3;
    d_row_w[pos] = d_topv[a];
    d_row_of[a] = pos;
}

// ---------------- GEMM1: gu[r, 0:1536] = x[src[r]] @ gate_up[e]^T ----------------
__global__ void gemm1_kernel(const float* __restrict__ x, const float* __restrict__ gup) {
    int bx = blockIdx.x;
    if (bx >= d_nmt) return;
    int e = d_tile_e[bx], base = d_tile_base[bx], lim = d_tile_lim[bx];
    int n0 = blockIdx.y * BN;
    __shared__ float As[BK][BM + 4];
    __shared__ float Bs[BK][BN + 4];
    int tid = threadIdx.x;
    int tm = tid >> 4, tn = tid & 15;
    int lrow = tid >> 2, lkq = tid & 3;
    bool valid = lrow < lim;
    const float* aptr = x + (valid ? (size_t)d_row_src[base + lrow] * HD : 0) + lkq * 4;
    const float* bptr = gup + ((size_t)e * TWOF + n0 + lrow) * HD + lkq * 4;
    float acc[4][4] = {};
    for (int k0 = 0; k0 < HD; k0 += BK) {
        float4 av = valid ? *(const float4*)(aptr + k0) : make_float4(0.f, 0.f, 0.f, 0.f);
        float4 bv = *(const float4*)(bptr + k0);
        __syncthreads();
        As[lkq * 4 + 0][lrow] = av.x; As[lkq * 4 + 1][lrow] = av.y;
        As[lkq * 4 + 2][lrow] = av.z; As[lkq * 4 + 3][lrow] = av.w;
        Bs[lkq * 4 + 0][lrow] = bv.x; Bs[lkq * 4 + 1][lrow] = bv.y;
        Bs[lkq * 4 + 2][lrow] = bv.z; Bs[lkq * 4 + 3][lrow] = bv.w;
        __syncthreads();
#pragma unroll
        for (int kk = 0; kk < BK; kk++) {
            float4 a = *(const float4*)&As[kk][tm * 4];
            float4 b = *(const float4*)&Bs[kk][tn * 4];
            float ar[4] = {a.x, a.y, a.z, a.w};
            float br[4] = {b.x, b.y, b.z, b.w};
#pragma unroll
            for (int i = 0; i < 4; i++)
#pragma unroll
                for (int j = 0; j < 4; j++) acc[i][j] += ar[i] * br[j];
        }
    }
#pragma unroll
    for (int i = 0; i < 4; i++) {
        int m = tm * 4 + i;
        if (m < lim) {
            float4 r = make_float4(acc[i][0], acc[i][1], acc[i][2], acc[i][3]);
            *(float4*)(d_gu + (size_t)(base + m) * TWOF + n0 + tn * 4) = r;
        }
    }
}

// ---------------- SwiGLU ----------------
__global__ void swiglu_kernel() {
    int idx = blockIdx.x * blockDim.x + threadIdx.x;
    if (idx >= d_totalpad * FI) return;
    int r = idx / FI, f = idx - r * FI;
    float g = d_gu[(size_t)r * TWOF + f];
    float u = d_gu[(size_t)r * TWOF + FI + f];
    d_hact[idx] = (g / (1.f + expf(-g))) * u;
}

// ---------------- GEMM2: y[r] = w[r] * (hact[r] @ down[e]^T) ----------------
__global__ void gemm2_kernel(const float* __restrict__ dwn) {
    int bx = blockIdx.x;
    if (bx >= d_nmt) return;
    int e = d_tile_e[bx], base = d_tile_base[bx], lim = d_tile_lim[bx];
    int n0 = blockIdx.y * BN;
    __shared__ float As[BK][BM + 4];
    __shared__ float Bs[BK][BN + 4];
    int tid = threadIdx.x;
    int tm = tid >> 4, tn = tid & 15;
    int lrow = tid >> 2, lkq = tid & 3;
    const float* aptr = d_hact + (size_t)(base + lrow) * FI + lkq * 4;
    const float* bptr = dwn + ((size_t)e * HD + n0 + lrow) * FI + lkq * 4;
    float acc[4][4] = {};
    for (int k0 = 0; k0 < FI; k0 += BK) {
        float4 av = *(const float4*)(aptr + k0);
        float4 bv = *(const float4*)(bptr + k0);
        __syncthreads();
        As[lkq * 4 + 0][lrow] = av.x; As[lkq * 4 + 1][lrow] = av.y;
        As[lkq * 4 + 2][lrow] = av.z; As[lkq * 4 + 3][lrow] = av.w;
        Bs[lkq * 4 + 0][lrow] = bv.x; Bs[lkq * 4 + 1][lrow] = bv.y;
        Bs[lkq * 4 + 2][lrow] = bv.z; Bs[lkq * 4 + 3][lrow] = bv.w;
        __syncthreads();
#pragma unroll
        for (int kk = 0; kk < BK; kk++) {
            float4 a = *(const float4*)&As[kk][tm * 4];
            float4 b = *(const float4*)&Bs[kk][tn * 4];
            float ar[4] = {a.x, a.y, a.z, a.w};
            float br[4] = {b.x, b.y, b.z, b.w};
#pragma unroll
            for (int i = 0; i < 4; i++)
#pragma unroll
                for (int j = 0; j < 4; j++) acc[i][j] += ar[i] * br[j];
        }
    }
#pragma unroll
    for (int i = 0; i < 4; i++) {
        int m = tm * 4 + i;
        if (m < lim) {
            float w = d_row_w[base + m];
            float4 r = make_float4(acc[i][0] * w, acc[i][1] * w, acc[i][2] * w, acc[i][3] * w);
            *(float4*)(d_y + (size_t)(base + m) * HD + n0 + tn * 4) = r;
        }
    }
}

// ---------------- deterministic combine: fixed slot order per token ----------------
__global__ void combine_kernel(float* __restrict__ out) {
    int t = blockIdx.x;
    __shared__ int rows[KTOP];
    if (threadIdx.x < KTOP) rows[threadIdx.x] = d_row_of[t * KTOP + threadIdx.x];
    __syncthreads();
    for (int h = threadIdx.x; h < HD; h += blockDim.x) {
        float s = 0.f;
#pragma unroll
        for (int k = 0; k < KTOP; k++) s += d_y[(size_t)rows[k] * HD + h];
        out[(size_t)t * HD + h] = s;
    }
}

// ---------------- launch ----------------
extern "C" void kernel_launch(void* const* d_in, const int* in_sizes, int n_in,
                              void* d_out, int out_size) {
    const float* x   = (const float*)d_in[0];   // [1, 2048, 2048]
    const float* gw  = (const float*)d_in[1];   // [64, 2048]
    const float* gup = (const float*)d_in[2];   // [64, 1536, 2048]
    const float* dwn = (const float*)d_in[3];   // [64, 2048, 768]
    const float* sim = (const float*)d_in[4];   // [64, 64]
    float* out = (float*)d_out;

    zero_kernel<<<1, 64>>>();
    router_kernel<<<T_TOK, 256>>>(x, gw);
    mapping_kernel<<<1, 64>>>(sim);
    reroute_kernel<<<(T_TOK * KTOP + 255) / 256, 256>>>();
    build_tiles_kernel<<<1, 1>>>();
    scatter_kernel<<<(T_TOK * KTOP + 255) / 256, 256>>>();
    gemm1_kernel<<<dim3(MAXMT, TWOF / BN), 256>>>(x, gup);
    swiglu_kernel<<<((size_t)CAP * FI + 255) / 256, 256>>>();
    gemm2_kernel<<<dim3(MAXMT, HD / BN), 256>>>(dwn);
    combine_kernel<<<T_TOK, 256>>>(out);
}

// round 2
// speedup vs baseline: 2.4179x; 2.4179x over previous
#include <cuda_runtime.h>
#include <math.h>
#include <stdint.h>

#define T_TOK 2048
#define NE 64
#define KTOP 8
#define SELK 4
#define HD 2048
#define FI 768
#define TWOF 1536
#define BM 64
#define MAXMT 320            // sum ceil(cnt/64) <= 16384/64 + 64
#define CAP 20480

// ---------------- scratch (device globals; no runtime allocation) ----------------
__device__ float d_topv[T_TOK * KTOP];
__device__ int   d_topi[T_TOK * KTOP];
__device__ int   d_rer[T_TOK * KTOP];
__device__ unsigned int d_pmask[2];
__device__ unsigned int d_smask[2];
__device__ int d_map[NE];
__device__ int d_counts[NE];
__device__ int d_padoff[NE];
__device__ int d_cursor[NE];
__device__ int d_tile_e[MAXMT];
__device__ int d_tile_base[MAXMT];
__device__ int d_tile_lim[MAXMT];
__device__ int d_nmt;
__device__ int d_totalpad;
__device__ int d_row_src[CAP];
__device__ float d_row_w[CAP];
__device__ int d_row_of[T_TOK * KTOP];
__device__ float d_hact[(size_t)CAP * FI];     // silu(gate)*up  (pads stay 0: never written)
__device__ float d_y[(size_t)CAP * HD];        // weighted expert outputs

// ---------------- tf32 helpers ----------------
__device__ __forceinline__ uint32_t f2tf(float f) {
    uint32_t u;
    asm("cvt.rna.tf32.f32 %0, %1;" : "=r"(u) : "f"(f));
    return u;
}
__device__ __forceinline__ uint4 cvt4(float4 v) {
    uint4 r; r.x = f2tf(v.x); r.y = f2tf(v.y); r.z = f2tf(v.z); r.w = f2tf(v.w);
    return r;
}
__device__ __forceinline__ void mma_tf32(float* c, const uint32_t* a, uint32_t b0, uint32_t b1) {
    asm volatile(
        "mma.sync.aligned.m16n8k8.row.col.f32.tf32.tf32.f32 "
        "{%0,%1,%2,%3}, {%4,%5,%6,%7}, {%8,%9}, {%0,%1,%2,%3};\n"
        : "+f"(c[0]), "+f"(c[1]), "+f"(c[2]), "+f"(c[3])
        : "r"(a[0]), "r"(a[1]), "r"(a[2]), "r"(a[3]), "r"(b0), "r"(b1));
}

// ---------------- reset mutable state ----------------
__global__ void zero_kernel() {
    int i = threadIdx.x;
    if (i < NE) d_counts[i] = 0;
    if (i < 2) { d_pmask[i] = 0u; d_smask[i] = 0u; }
}

// ---------------- router ----------------
__global__ void router_kernel(const float* __restrict__ x, const float* __restrict__ gw) {
    __shared__ float sx[HD];
    __shared__ float sl[NE];
    int t = blockIdx.x;
    const float* xr = x + (size_t)t * HD;
    for (int i = threadIdx.x; i < HD; i += blockDim.x) sx[i] = xr[i];
    __syncthreads();

    int e   = threadIdx.x >> 2;
    int sub = threadIdx.x & 3;
    const float4* wp = (const float4*)(gw + (size_t)e * HD + sub * (HD / 4));
    const float4* xp = (const float4*)(sx + sub * (HD / 4));
    float s = 0.f;
#pragma unroll 4
    for (int i = 0; i < HD / 16; i++) {
        float4 a = xp[i]; float4 w = wp[i];
        s += a.x * w.x + a.y * w.y + a.z * w.z + a.w * w.w;
    }
    s += __shfl_xor_sync(0xffffffffu, s, 1);
    s += __shfl_xor_sync(0xffffffffu, s, 2);
    if (sub == 0) sl[e] = s;
    __syncthreads();

    if (threadIdx.x < 32) {
        int lane = threadIdx.x;
        float v0 = sl[lane], v1 = sl[lane + 32];
        float m = fmaxf(v0, v1);
        for (int off = 16; off; off >>= 1) m = fmaxf(m, __shfl_xor_sync(0xffffffffu, m, off));
        float e0 = expf(v0 - m), e1 = expf(v1 - m);
        float ss = e0 + e1;
        for (int off = 16; off; off >>= 1) ss += __shfl_xor_sync(0xffffffffu, ss, off);
        float p0 = e0 / ss, p1 = e1 / ss;

        float tv[KTOP]; int ti[KTOP];
#pragma unroll
        for (int k = 0; k < KTOP; k++) {
            float b; int bi;
            if (p0 >= p1) { b = p0; bi = lane; } else { b = p1; bi = lane + 32; }
            for (int off = 16; off; off >>= 1) {
                float ob = __shfl_xor_sync(0xffffffffu, b, off);
                int obi  = __shfl_xor_sync(0xffffffffu, bi, off);
                if (ob > b || (ob == b && obi < bi)) { b = ob; bi = obi; }
            }
            tv[k] = b; ti[k] = bi;
            if (bi < 32) { if (lane == bi) p0 = -1.f; }
            else         { if (lane == bi - 32) p1 = -1.f; }
        }
        if (lane == 0) {
            float tsum = 0.f;
#pragma unroll
            for (int k = 0; k < KTOP; k++) tsum += tv[k];
            tsum = fmaxf(tsum, 1e-12f);
#pragma unroll
            for (int k = 0; k < KTOP; k++) {
                d_topv[t * KTOP + k] = tv[k] / tsum;
                d_topi[t * KTOP + k] = ti[k];
                int b = ti[k];
                if (k < SELK) atomicOr(&d_pmask[b >> 5], 1u << (b & 31));
                else          atomicOr(&d_smask[b >> 5], 1u << (b & 31));
            }
        }
    }
}

// ---------------- SERE mapping ----------------
__global__ void mapping_kernel(const float* __restrict__ sim) {
    int e = threadIdx.x;
    if (e >= NE) return;
    unsigned pm0 = d_pmask[0], pm1 = d_pmask[1];
    unsigned sm0 = d_smask[0], sm1 = d_smask[1];
    bool prim = (e < 32) ? ((pm0 >> e) & 1) : ((pm1 >> (e - 32)) & 1);
    bool sec  = (e < 32) ? ((sm0 >> e) & 1) : ((sm1 >> (e - 32)) & 1);
    int best = 0; float bs = -INFINITY;
    for (int p = 0; p < NE; p++) {
        bool pp = (p < 32) ? ((pm0 >> p) & 1) : ((pm1 >> (p - 32)) & 1);
        if (!pp) continue;
        float v = (p == e) ? 1.0f : sim[e * NE + p];
        if (v > bs) { bs = v; best = p; }
    }
    int mp = e;
    if (sec && !prim && bs >= 0.5f) mp = best;
    d_map[e] = mp;
}

// ---------------- reroute + counts ----------------
__global__ void reroute_kernel() {
    int a = blockIdx.x * blockDim.x + threadIdx.x;
    if (a >= T_TOK * KTOP) return;
    int k = a & 7;
    int e0 = d_topi[a];
    int e = (k < SELK) ? e0 : d_map[e0];
    d_rer[a] = e;
    atomicAdd(&d_counts[e], 1);
}

// ---------------- tile table ----------------
__global__ void build_tiles_kernel() {
    if (threadIdx.x != 0 || blockIdx.x != 0) return;
    int off = 0, nt = 0;
    for (int e = 0; e < NE; e++) {
        d_padoff[e] = off;
        d_cursor[e] = 0;
        int c = d_counts[e];
        int mt = (c + BM - 1) / BM;
        for (int i = 0; i < mt; i++) {
            d_tile_e[nt] = e;
            d_tile_base[nt] = off + i * BM;
            int lm = c - i * BM; if (lm > BM) lm = BM;
            d_tile_lim[nt] = lm;
            nt++;
        }
        off += mt * BM;
    }
    d_nmt = nt;
    d_totalpad = off;
}

// ---------------- scatter ----------------
__global__ void scatter_kernel() {
    int a = blockIdx.x * blockDim.x + threadIdx.x;
    if (a >= T_TOK * KTOP) return;
    int e = d_rer[a];
    int pos = d_padoff[e] + atomicAdd(&d_cursor[e], 1);
    d_row_src[pos] = a >> 3;
    d_row_w[pos] = d_topv[a];
    d_row_of[a] = pos;
}

// ======================================================================
// GEMM1 (tf32 tensor cores) + fused SwiGLU:
//   hact[r, n0:n0+64] = silu(x[src]·Wg[n0..]) * (x[src]·Wu[n0..])
// Block: 64 rows × 64 gate cols (+ matching 64 up cols). 4 warps, 32×32 warp tiles.
// ======================================================================
__global__ __launch_bounds__(128) void gemm1_kernel(const float* __restrict__ x,
                                                    const float* __restrict__ gup) {
    int bx = blockIdx.x;
    if (bx >= d_nmt) return;
    int e = d_tile_e[bx], base = d_tile_base[bx], lim = d_tile_lim[bx];
    int n0 = blockIdx.y * 64;          // gate column base in [0, 768)

    __shared__ __align__(16) uint32_t As[2][64][20];
    __shared__ __align__(16) uint32_t Bs[2][128][20];   // rows 0-63 gate, 64-127 up
    __shared__ int srow[64];

    int tid = threadIdx.x;
    if (tid < 64) srow[tid] = (tid < lim) ? d_row_src[base + tid] : -1;
    __syncthreads();

    int kq = tid & 3;
    int r0 = tid >> 2;                 // 0..31
    const float* aptr[2];
#pragma unroll
    for (int i = 0; i < 2; i++) {
        int s = srow[r0 + i * 32];
        aptr[i] = (s >= 0) ? (x + (size_t)s * HD + kq * 4) : nullptr;
    }
    const float* bptr[4];
#pragma unroll
    for (int i = 0; i < 4; i++) {
        int row = r0 + i * 32;
        int br = (row < 64) ? (n0 + row) : (FI + n0 + (row - 64));
        bptr[i] = gup + ((size_t)e * TWOF + br) * HD + kq * 4;
    }

    int warp = tid >> 5, lane = tid & 31;
    int wm = warp >> 1, wn = warp & 1;
    int g = lane >> 2, tg = lane & 3;

    float cg[2][4][4] = {};
    float cu[2][4][4] = {};

    float4 ra[2], rb[4];
#pragma unroll
    for (int i = 0; i < 2; i++) ra[i] = aptr[i] ? *(const float4*)aptr[i] : make_float4(0, 0, 0, 0);
#pragma unroll
    for (int i = 0; i < 4; i++) rb[i] = *(const float4*)bptr[i];
#pragma unroll
    for (int i = 0; i < 2; i++) *(uint4*)&As[0][r0 + i * 32][kq * 4] = cvt4(ra[i]);
#pragma unroll
    for (int i = 0; i < 4; i++) *(uint4*)&Bs[0][r0 + i * 32][kq * 4] = cvt4(rb[i]);
    __syncthreads();

    int buf = 0;
    const int NIT = HD / 16;           // 128
    for (int it = 0; it < NIT; it++) {
        if (it + 1 < NIT) {
            int kn = (it + 1) * 16;
#pragma unroll
            for (int i = 0; i < 2; i++)
                ra[i] = aptr[i] ? *(const float4*)(aptr[i] + kn) : make_float4(0, 0, 0, 0);
#pragma unroll
            for (int i = 0; i < 4; i++) rb[i] = *(const float4*)(bptr[i] + kn);
        }
#pragma unroll
        for (int kk = 0; kk < 16; kk += 8) {
            uint32_t af[2][4];
#pragma unroll
            for (int mi = 0; mi < 2; mi++) {
                int r = wm * 32 + mi * 16;
                af[mi][0] = As[buf][r + g][kk + tg];
                af[mi][1] = As[buf][r + g + 8][kk + tg];
                af[mi][2] = As[buf][r + g][kk + tg + 4];
                af[mi][3] = As[buf][r + g + 8][kk + tg + 4];
            }
#pragma unroll
            for (int ni = 0; ni < 4; ni++) {
                int c = wn * 32 + ni * 8 + g;
                uint32_t b0 = Bs[buf][c][kk + tg],       b1 = Bs[buf][c][kk + tg + 4];
                uint32_t u0 = Bs[buf][64 + c][kk + tg],  u1 = Bs[buf][64 + c][kk + tg + 4];
#pragma unroll
                for (int mi = 0; mi < 2; mi++) {
                    mma_tf32(cg[mi][ni], af[mi], b0, b1);
                    mma_tf32(cu[mi][ni], af[mi], u0, u1);
                }
            }
        }
        if (it + 1 < NIT) {
            int d = buf ^ 1;
#pragma unroll
            for (int i = 0; i < 2; i++) *(uint4*)&As[d][r0 + i * 32][kq * 4] = cvt4(ra[i]);
#pragma unroll
            for (int i = 0; i < 4; i++) *(uint4*)&Bs[d][r0 + i * 32][kq * 4] = cvt4(rb[i]);
        }
        __syncthreads();
        buf ^= 1;
    }

    // fused SwiGLU epilogue
#pragma unroll
    for (int mi = 0; mi < 2; mi++) {
#pragma unroll
        for (int half = 0; half < 2; half++) {
            int row = wm * 32 + mi * 16 + g + half * 8;
            if (row < lim) {
                float* dst = d_hact + (size_t)(base + row) * FI + n0 + wn * 32;
#pragma unroll
                for (int ni = 0; ni < 4; ni++) {
                    float g0 = cg[mi][ni][half * 2 + 0], g1 = cg[mi][ni][half * 2 + 1];
                    float u0 = cu[mi][ni][half * 2 + 0], u1 = cu[mi][ni][half * 2 + 1];
                    float h0 = g0 / (1.f + expf(-g0)) * u0;
                    float h1 = g1 / (1.f + expf(-g1)) * u1;
                    *(float2*)(dst + ni * 8 + tg * 2) = make_float2(h0, h1);
                }
            }
        }
    }
}

// ======================================================================
// GEMM2 (tf32): y[r, n0:n0+64] = w[r] * (hact[r] @ down[e]^T)
// ======================================================================
__global__ __launch_bounds__(128) void gemm2_kernel(const float* __restrict__ dwn) {
    int bx = blockIdx.x;
    if (bx >= d_nmt) return;
    int e = d_tile_e[bx], base = d_tile_base[bx], lim = d_tile_lim[bx];
    int n0 = blockIdx.y * 64;          // output column in [0, 2048)

    __shared__ __align__(16) uint32_t As[2][64][20];
    __shared__ __align__(16) uint32_t Bs[2][64][20];

    int tid = threadIdx.x;
    int kq = tid & 3;
    int r0 = tid >> 2;
    const float* aptr[2];
#pragma unroll
    for (int i = 0; i < 2; i++)
        aptr[i] = d_hact + (size_t)(base + r0 + i * 32) * FI + kq * 4;
    const float* bptr[2];
#pragma unroll
    for (int i = 0; i < 2; i++)
        bptr[i] = dwn + ((size_t)e * HD + n0 + r0 + i * 32) * FI + kq * 4;

    int warp = tid >> 5, lane = tid & 31;
    int wm = warp >> 1, wn = warp & 1;
    int g = lane >> 2, tg = lane & 3;

    float cc[2][4][4] = {};

    float4 ra[2], rb[2];
#pragma unroll
    for (int i = 0; i < 2; i++) { ra[i] = *(const float4*)aptr[i]; rb[i] = *(const float4*)bptr[i]; }
#pragma unroll
    for (int i = 0; i < 2; i++) {
        *(uint4*)&As[0][r0 + i * 32][kq * 4] = cvt4(ra[i]);
        *(uint4*)&Bs[0][r0 + i * 32][kq * 4] = cvt4(rb[i]);
    }
    __syncthreads();

    int buf = 0;
    const int NIT = FI / 16;           // 48
    for (int it = 0; it < NIT; it++) {
        if (it + 1 < NIT) {
            int kn = (it + 1) * 16;
#pragma unroll
            for (int i = 0; i < 2; i++) {
                ra[i] = *(const float4*)(aptr[i] + kn);
                rb[i] = *(const float4*)(bptr[i] + kn);
            }
        }
#pragma unroll
        for (int kk = 0; kk < 16; kk += 8) {
            uint32_t af[2][4];
#pragma unroll
            for (int mi = 0; mi < 2; mi++) {
                int r = wm * 32 + mi * 16;
                af[mi][0] = As[buf][r + g][kk + tg];
                af[mi][1] = As[buf][r + g + 8][kk + tg];
                af[mi][2] = As[buf][r + g][kk + tg + 4];
                af[mi][3] = As[buf][r + g + 8][kk + tg + 4];
            }
#pragma unroll
            for (int ni = 0; ni < 4; ni++) {
                int c = wn * 32 + ni * 8 + g;
                uint32_t b0 = Bs[buf][c][kk + tg], b1 = Bs[buf][c][kk + tg + 4];
#pragma unroll
                for (int mi = 0; mi < 2; mi++)
                    mma_tf32(cc[mi][ni], af[mi], b0, b1);
            }
        }
        if (it + 1 < NIT) {
            int d = buf ^ 1;
#pragma unroll
            for (int i = 0; i < 2; i++) {
                *(uint4*)&As[d][r0 + i * 32][kq * 4] = cvt4(ra[i]);
                *(uint4*)&Bs[d][r0 + i * 32][kq * 4] = cvt4(rb[i]);
            }
        }
        __syncthreads();
        buf ^= 1;
    }

#pragma unroll
    for (int mi = 0; mi < 2; mi++) {
#pragma unroll
        for (int half = 0; half < 2; half++) {
            int row = wm * 32 + mi * 16 + g + half * 8;
            if (row < lim) {
                float w = d_row_w[base + row];
                float* dst = d_y + (size_t)(base + row) * HD + n0 + wn * 32;
#pragma unroll
                for (int ni = 0; ni < 4; ni++) {
                    float v0 = cc[mi][ni][half * 2 + 0] * w;
                    float v1 = cc[mi][ni][half * 2 + 1] * w;
                    *(float2*)(dst + ni * 8 + tg * 2) = make_float2(v0, v1);
                }
            }
        }
    }
}

// ---------------- deterministic combine ----------------
__global__ void combine_kernel(float* __restrict__ out) {
    int t = blockIdx.x;
    __shared__ int rows[KTOP];
    if (threadIdx.x < KTOP) rows[threadIdx.x] = d_row_of[t * KTOP + threadIdx.x];
    __syncthreads();
    for (int h = threadIdx.x; h < HD; h += blockDim.x) {
        float s = 0.f;
#pragma unroll
        for (int k = 0; k < KTOP; k++) s += d_y[(size_t)rows[k] * HD + h];
        out[(size_t)t * HD + h] = s;
    }
}

// ---------------- launch ----------------
extern "C" void kernel_launch(void* const* d_in, const int* in_sizes, int n_in,
                              void* d_out, int out_size) {
    const float* x   = (const float*)d_in[0];   // [1, 2048, 2048]
    const float* gw  = (const float*)d_in[1];   // [64, 2048]
    const float* gup = (const float*)d_in[2];   // [64, 1536, 2048]
    const float* dwn = (const float*)d_in[3];   // [64, 2048, 768]
    const float* sim = (const float*)d_in[4];   // [64, 64]
    float* out = (float*)d_out;

    zero_kernel<<<1, 64>>>();
    router_kernel<<<T_TOK, 256>>>(x, gw);
    mapping_kernel<<<1, 64>>>(sim);
    reroute_kernel<<<(T_TOK * KTOP + 255) / 256, 256>>>();
    build_tiles_kernel<<<1, 1>>>();
    scatter_kernel<<<(T_TOK * KTOP + 255) / 256, 256>>>();
    gemm1_kernel<<<dim3(MAXMT, FI / 64), 128>>>(x, gup);
    gemm2_kernel<<<dim3(MAXMT, HD / 64), 128>>>(dwn);
    combine_kernel<<<T_TOK, 256>>>(out);
}

// round 3
// speedup vs baseline: 2.4204x; 1.0010x over previous
#include <cuda_runtime.h>
#include <math.h>
#include <stdint.h>

#define T_TOK 2048
#define NE 64
#define KTOP 8
#define SELK 4
#define HD 2048
#define FI 768
#define TWOF 1536
#define BM 64
#define MAXMT 320            // sum ceil(cnt/64) <= 16384/64 + 64
#define CAP 20480

// ---------------- scratch (device globals; no runtime allocation) ----------------
__device__ float d_topv[T_TOK * KTOP];
__device__ int   d_topi[T_TOK * KTOP];
__device__ int   d_rer[T_TOK * KTOP];
__device__ unsigned int d_pmask[2];
__device__ unsigned int d_smask[2];
__device__ int d_map[NE];
__device__ int d_counts[NE];
__device__ int d_padoff[NE];
__device__ int d_cursor[NE];
__device__ int d_tile_e[MAXMT];
__device__ int d_tile_base[MAXMT];
__device__ int d_tile_lim[MAXMT];
__device__ int d_nmt;
__device__ int d_totalpad;
__device__ int d_row_src[CAP];
__device__ float d_row_w[CAP];
__device__ int d_row_of[T_TOK * KTOP];
__device__ float d_hact[(size_t)CAP * FI];     // silu(gate)*up  (pads stay 0: never written)
__device__ float d_y[(size_t)CAP * HD];        // weighted expert outputs

// ---------------- tf32 helpers ----------------
__device__ __forceinline__ uint32_t f2tf(float f) {
    uint32_t u;
    asm("cvt.rna.tf32.f32 %0, %1;" : "=r"(u) : "f"(f));
    return u;
}
__device__ __forceinline__ uint4 cvt4(float4 v) {
    uint4 r; r.x = f2tf(v.x); r.y = f2tf(v.y); r.z = f2tf(v.z); r.w = f2tf(v.w);
    return r;
}
__device__ __forceinline__ void mma_tf32(float* c, const uint32_t* a, uint32_t b0, uint32_t b1) {
    asm volatile(
        "mma.sync.aligned.m16n8k8.row.col.f32.tf32.tf32.f32 "
        "{%0,%1,%2,%3}, {%4,%5,%6,%7}, {%8,%9}, {%0,%1,%2,%3};\n"
        : "+f"(c[0]), "+f"(c[1]), "+f"(c[2]), "+f"(c[3])
        : "r"(a[0]), "r"(a[1]), "r"(a[2]), "r"(a[3]), "r"(b0), "r"(b1));
}

// ---------------- reset mutable state ----------------
__global__ void zero_kernel() {
    int i = threadIdx.x;
    if (i < NE) d_counts[i] = 0;
    if (i < 2) { d_pmask[i] = 0u; d_smask[i] = 0u; }
}

// ---------------- router ----------------
__global__ void router_kernel(const float* __restrict__ x, const float* __restrict__ gw) {
    __shared__ float sx[HD];
    __shared__ float sl[NE];
    int t = blockIdx.x;
    const float* xr = x + (size_t)t * HD;
    for (int i = threadIdx.x; i < HD; i += blockDim.x) sx[i] = xr[i];
    __syncthreads();

    int e   = threadIdx.x >> 2;
    int sub = threadIdx.x & 3;
    const float4* wp = (const float4*)(gw + (size_t)e * HD + sub * (HD / 4));
    const float4* xp = (const float4*)(sx + sub * (HD / 4));
    float s = 0.f;
#pragma unroll 4
    for (int i = 0; i < HD / 16; i++) {
        float4 a = xp[i]; float4 w = wp[i];
        s += a.x * w.x + a.y * w.y + a.z * w.z + a.w * w.w;
    }
    s += __shfl_xor_sync(0xffffffffu, s, 1);
    s += __shfl_xor_sync(0xffffffffu, s, 2);
    if (sub == 0) sl[e] = s;
    __syncthreads();

    if (threadIdx.x < 32) {
        int lane = threadIdx.x;
        float v0 = sl[lane], v1 = sl[lane + 32];
        float m = fmaxf(v0, v1);
        for (int off = 16; off; off >>= 1) m = fmaxf(m, __shfl_xor_sync(0xffffffffu, m, off));
        float e0 = expf(v0 - m), e1 = expf(v1 - m);
        float ss = e0 + e1;
        for (int off = 16; off; off >>= 1) ss += __shfl_xor_sync(0xffffffffu, ss, off);
        float p0 = e0 / ss, p1 = e1 / ss;

        float tv[KTOP]; int ti[KTOP];
#pragma unroll
        for (int k = 0; k < KTOP; k++) {
            float b; int bi;
            if (p0 >= p1) { b = p0; bi = lane; } else { b = p1; bi = lane + 32; }
            for (int off = 16; off; off >>= 1) {
                float ob = __shfl_xor_sync(0xffffffffu, b, off);
                int obi  = __shfl_xor_sync(0xffffffffu, bi, off);
                if (ob > b || (ob == b && obi < bi)) { b = ob; bi = obi; }
            }
            tv[k] = b; ti[k] = bi;
            if (bi < 32) { if (lane == bi) p0 = -1.f; }
            else         { if (lane == bi - 32) p1 = -1.f; }
        }
        if (lane == 0) {
            float tsum = 0.f;
#pragma unroll
            for (int k = 0; k < KTOP; k++) tsum += tv[k];
            tsum = fmaxf(tsum, 1e-12f);
#pragma unroll
            for (int k = 0; k < KTOP; k++) {
                d_topv[t * KTOP + k] = tv[k] / tsum;
                d_topi[t * KTOP + k] = ti[k];
                int b = ti[k];
                if (k < SELK) atomicOr(&d_pmask[b >> 5], 1u << (b & 31));
                else          atomicOr(&d_smask[b >> 5], 1u << (b & 31));
            }
        }
    }
}

// ---------------- SERE mapping ----------------
__global__ void mapping_kernel(const float* __restrict__ sim) {
    int e = threadIdx.x;
    if (e >= NE) return;
    unsigned pm0 = d_pmask[0], pm1 = d_pmask[1];
    unsigned sm0 = d_smask[0], sm1 = d_smask[1];
    bool prim = (e < 32) ? ((pm0 >> e) & 1) : ((pm1 >> (e - 32)) & 1);
    bool sec  = (e < 32) ? ((sm0 >> e) & 1) : ((sm1 >> (e - 32)) & 1);
    int best = 0; float bs = -INFINITY;
    for (int p = 0; p < NE; p++) {
        bool pp = (p < 32) ? ((pm0 >> p) & 1) : ((pm1 >> (p - 32)) & 1);
        if (!pp) continue;
        float v = (p == e) ? 1.0f : sim[e * NE + p];
        if (v > bs) { bs = v; best = p; }
    }
    int mp = e;
    if (sec && !prim && bs >= 0.5f) mp = best;
    d_map[e] = mp;
}

// ---------------- reroute + counts ----------------
__global__ void reroute_kernel() {
    int a = blockIdx.x * blockDim.x + threadIdx.x;
    if (a >= T_TOK * KTOP) return;
    int k = a & 7;
    int e0 = d_topi[a];
    int e = (k < SELK) ? e0 : d_map[e0];
    d_rer[a] = e;
    atomicAdd(&d_counts[e], 1);
}

// ---------------- tile table ----------------
__global__ void build_tiles_kernel() {
    if (threadIdx.x != 0 || blockIdx.x != 0) return;
    int off = 0, nt = 0;
    for (int e = 0; e < NE; e++) {
        d_padoff[e] = off;
        d_cursor[e] = 0;
        int c = d_counts[e];
        int mt = (c + BM - 1) / BM;
        for (int i = 0; i < mt; i++) {
            d_tile_e[nt] = e;
            d_tile_base[nt] = off + i * BM;
            int lm = c - i * BM; if (lm > BM) lm = BM;
            d_tile_lim[nt] = lm;
            nt++;
        }
        off += mt * BM;
    }
    d_nmt = nt;
    d_totalpad = off;
}

// ---------------- scatter ----------------
__global__ void scatter_kernel() {
    int a = blockIdx.x * blockDim.x + threadIdx.x;
    if (a >= T_TOK * KTOP) return;
    int e = d_rer[a];
    int pos = d_padoff[e] + atomicAdd(&d_cursor[e], 1);
    d_row_src[pos] = a >> 3;
    d_row_w[pos] = d_topv[a];
    d_row_of[a] = pos;
}

// ======================================================================
// GEMM1 (tf32 tensor cores) + fused SwiGLU:
//   hact[r, n0:n0+64] = silu(x[src]·Wg[n0..]) * (x[src]·Wu[n0..])
// Block: 64 rows × 64 gate cols (+ matching 64 up cols). 4 warps, 32×32 warp tiles.
// ======================================================================
__global__ __launch_bounds__(128) void gemm1_kernel(const float* __restrict__ x,
                                                    const float* __restrict__ gup) {
    int bx = blockIdx.x;
    if (bx >= d_nmt) return;
    int e = d_tile_e[bx], base = d_tile_base[bx], lim = d_tile_lim[bx];
    int n0 = blockIdx.y * 64;          // gate column base in [0, 768)

    __shared__ __align__(16) uint32_t As[2][64][20];
    __shared__ __align__(16) uint32_t Bs[2][128][20];   // rows 0-63 gate, 64-127 up
    __shared__ int srow[64];

    int tid = threadIdx.x;
    if (tid < 64) srow[tid] = (tid < lim) ? d_row_src[base + tid] : -1;
    __syncthreads();

    int kq = tid & 3;
    int r0 = tid >> 2;                 // 0..31
    const float* aptr[2];
#pragma unroll
    for (int i = 0; i < 2; i++) {
        int s = srow[r0 + i * 32];
        aptr[i] = (s >= 0) ? (x + (size_t)s * HD + kq * 4) : nullptr;
    }
    const float* bptr[4];
#pragma unroll
    for (int i = 0; i < 4; i++) {
        int row = r0 + i * 32;
        int br = (row < 64) ? (n0 + row) : (FI + n0 + (row - 64));
        bptr[i] = gup + ((size_t)e * TWOF + br) * HD + kq * 4;
    }

    int warp = tid >> 5, lane = tid & 31;
    int wm = warp >> 1, wn = warp & 1;
    int g = lane >> 2, tg = lane & 3;

    float cg[2][4][4] = {};
    float cu[2][4][4] = {};

    float4 ra[2], rb[4];
#pragma unroll
    for (int i = 0; i < 2; i++) ra[i] = aptr[i] ? *(const float4*)aptr[i] : make_float4(0, 0, 0, 0);
#pragma unroll
    for (int i = 0; i < 4; i++) rb[i] = *(const float4*)bptr[i];
#pragma unroll
    for (int i = 0; i < 2; i++) *(uint4*)&As[0][r0 + i * 32][kq * 4] = cvt4(ra[i]);
#pragma unroll
    for (int i = 0; i < 4; i++) *(uint4*)&Bs[0][r0 + i * 32][kq * 4] = cvt4(rb[i]);
    __syncthreads();

    int buf = 0;
    const int NIT = HD / 16;           // 128
    for (int it = 0; it < NIT; it++) {
        if (it + 1 < NIT) {
            int kn = (it + 1) * 16;
#pragma unroll
            for (int i = 0; i < 2; i++)
                ra[i] = aptr[i] ? *(const float4*)(aptr[i] + kn) : make_float4(0, 0, 0, 0);
#pragma unroll
            for (int i = 0; i < 4; i++) rb[i] = *(const float4*)(bptr[i] + kn);
        }
#pragma unroll
        for (int kk = 0; kk < 16; kk += 8) {
            uint32_t af[2][4];
#pragma unroll
            for (int mi = 0; mi < 2; mi++) {
                int r = wm * 32 + mi * 16;
                af[mi][0] = As[buf][r + g][kk + tg];
                af[mi][1] = As[buf][r + g + 8][kk + tg];
                af[mi][2] = As[buf][r + g][kk + tg + 4];
                af[mi][3] = As[buf][r + g + 8][kk + tg + 4];
            }
#pragma unroll
            for (int ni = 0; ni < 4; ni++) {
                int c = wn * 32 + ni * 8 + g;
                uint32_t b0 = Bs[buf][c][kk + tg],       b1 = Bs[buf][c][kk + tg + 4];
                uint32_t u0 = Bs[buf][64 + c][kk + tg],  u1 = Bs[buf][64 + c][kk + tg + 4];
#pragma unroll
                for (int mi = 0; mi < 2; mi++) {
                    mma_tf32(cg[mi][ni], af[mi], b0, b1);
                    mma_tf32(cu[mi][ni], af[mi], u0, u1);
                }
            }
        }
        if (it + 1 < NIT) {
            int d = buf ^ 1;
#pragma unroll
            for (int i = 0; i < 2; i++) *(uint4*)&As[d][r0 + i * 32][kq * 4] = cvt4(ra[i]);
#pragma unroll
            for (int i = 0; i < 4; i++) *(uint4*)&Bs[d][r0 + i * 32][kq * 4] = cvt4(rb[i]);
        }
        __syncthreads();
        buf ^= 1;
    }

    // fused SwiGLU epilogue
#pragma unroll
    for (int mi = 0; mi < 2; mi++) {
#pragma unroll
        for (int half = 0; half < 2; half++) {
            int row = wm * 32 + mi * 16 + g + half * 8;
            if (row < lim) {
                float* dst = d_hact + (size_t)(base + row) * FI + n0 + wn * 32;
#pragma unroll
                for (int ni = 0; ni < 4; ni++) {
                    float g0 = cg[mi][ni][half * 2 + 0], g1 = cg[mi][ni][half * 2 + 1];
                    float u0 = cu[mi][ni][half * 2 + 0], u1 = cu[mi][ni][half * 2 + 1];
                    float h0 = g0 / (1.f + expf(-g0)) * u0;
                    float h1 = g1 / (1.f + expf(-g1)) * u1;
                    *(float2*)(dst + ni * 8 + tg * 2) = make_float2(h0, h1);
                }
            }
        }
    }
}

// ======================================================================
// GEMM2 (tf32): y[r, n0:n0+64] = w[r] * (hact[r] @ down[e]^T)
// ======================================================================
__global__ __launch_bounds__(128) void gemm2_kernel(const float* __restrict__ dwn) {
    int bx = blockIdx.x;
    if (bx >= d_nmt) return;
    int e = d_tile_e[bx], base = d_tile_base[bx], lim = d_tile_lim[bx];
    int n0 = blockIdx.y * 64;          // output column in [0, 2048)

    __shared__ __align__(16) uint32_t As[2][64][20];
    __shared__ __align__(16) uint32_t Bs[2][64][20];

    int tid = threadIdx.x;
    int kq = tid & 3;
    int r0 = tid >> 2;
    const float* aptr[2];
#pragma unroll
    for (int i = 0; i < 2; i++)
        aptr[i] = d_hact + (size_t)(base + r0 + i * 32) * FI + kq * 4;
    const float* bptr[2];
#pragma unroll
    for (int i = 0; i < 2; i++)
        bptr[i] = dwn + ((size_t)e * HD + n0 + r0 + i * 32) * FI + kq * 4;

    int warp = tid >> 5, lane = tid & 31;
    int wm = warp >> 1, wn = warp & 1;
    int g = lane >> 2, tg = lane & 3;

    float cc[2][4][4] = {};

    float4 ra[2], rb[2];
#pragma unroll
    for (int i = 0; i < 2; i++) { ra[i] = *(const float4*)aptr[i]; rb[i] = *(const float4*)bptr[i]; }
#pragma unroll
    for (int i = 0; i < 2; i++) {
        *(uint4*)&As[0][r0 + i * 32][kq * 4] = cvt4(ra[i]);
        *(uint4*)&Bs[0][r0 + i * 32][kq * 4] = cvt4(rb[i]);
    }
    __syncthreads();

    int buf = 0;
    const int NIT = FI / 16;           // 48
    for (int it = 0; it < NIT; it++) {
        if (it + 1 < NIT) {
            int kn = (it + 1) * 16;
#pragma unroll
            for (int i = 0; i < 2; i++) {
                ra[i] = *(const float4*)(aptr[i] + kn);
                rb[i] = *(const float4*)(bptr[i] + kn);
            }
        }
#pragma unroll
        for (int kk = 0; kk < 16; kk += 8) {
            uint32_t af[2][4];
#pragma unroll
            for (int mi = 0; mi < 2; mi++) {
                int r = wm * 32 + mi * 16;
                af[mi][0] = As[buf][r + g][kk + tg];
                af[mi][1] = As[buf][r + g + 8][kk + tg];
                af[mi][2] = As[buf][r + g][kk + tg + 4];
                af[mi][3] = As[buf][r + g + 8][kk + tg + 4];
            }
#pragma unroll
            for (int ni = 0; ni < 4; ni++) {
                int c = wn * 32 + ni * 8 + g;
                uint32_t b0 = Bs[buf][c][kk + tg], b1 = Bs[buf][c][kk + tg + 4];
#pragma unroll
                for (int mi = 0; mi < 2; mi++)
                    mma_tf32(cc[mi][ni], af[mi], b0, b1);
            }
        }
        if (it + 1 < NIT) {
            int d = buf ^ 1;
#pragma unroll
            for (int i = 0; i < 2; i++) {
                *(uint4*)&As[d][r0 + i * 32][kq * 4] = cvt4(ra[i]);
                *(uint4*)&Bs[d][r0 + i * 32][kq * 4] = cvt4(rb[i]);
            }
        }
        __syncthreads();
        buf ^= 1;
    }

#pragma unroll
    for (int mi = 0; mi < 2; mi++) {
#pragma unroll
        for (int half = 0; half < 2; half++) {
            int row = wm * 32 + mi * 16 + g + half * 8;
            if (row < lim) {
                float w = d_row_w[base + row];
                float* dst = d_y + (size_t)(base + row) * HD + n0 + wn * 32;
#pragma unroll
                for (int ni = 0; ni < 4; ni++) {
                    float v0 = cc[mi][ni][half * 2 + 0] * w;
                    float v1 = cc[mi][ni][half * 2 + 1] * w;
                    *(float2*)(dst + ni * 8 + tg * 2) = make_float2(v0, v1);
                }
            }
        }
    }
}

// ---------------- deterministic combine ----------------
__global__ void combine_kernel(float* __restrict__ out) {
    int t = blockIdx.x;
    __shared__ int rows[KTOP];
    if (threadIdx.x < KTOP) rows[threadIdx.x] = d_row_of[t * KTOP + threadIdx.x];
    __syncthreads();
    for (int h = threadIdx.x; h < HD; h += blockDim.x) {
        float s = 0.f;
#pragma unroll
        for (int k = 0; k < KTOP; k++) s += d_y[(size_t)rows[k] * HD + h];
        out[(size_t)t * HD + h] = s;
    }
}

// ---------------- launch ----------------
extern "C" void kernel_launch(void* const* d_in, const int* in_sizes, int n_in,
                              void* d_out, int out_size) {
    const float* x   = (const float*)d_in[0];   // [1, 2048, 2048]
    const float* gw  = (const float*)d_in[1];   // [64, 2048]
    const float* gup = (const float*)d_in[2];   // [64, 1536, 2048]
    const float* dwn = (const float*)d_in[3];   // [64, 2048, 768]
    const float* sim = (const float*)d_in[4];   // [64, 64]
    float* out = (float*)d_out;

    zero_kernel<<<1, 64>>>();
    router_kernel<<<T_TOK, 256>>>(x, gw);
    mapping_kernel<<<1, 64>>>(sim);
    reroute_kernel<<<(T_TOK * KTOP + 255) / 256, 256>>>();
    build_tiles_kernel<<<1, 1>>>();
    scatter_kernel<<<(T_TOK * KTOP + 255) / 256, 256>>>();
    gemm1_kernel<<<dim3(MAXMT, FI / 64), 128>>>(x, gup);
    gemm2_kernel<<<dim3(MAXMT, HD / 64), 128>>>(dwn);
    combine_kernel<<<T_TOK, 256>>>(out);
}